// round 13
// baseline (speedup 1.0000x reference)
#include <cuda_runtime.h>
#include <math.h>

#define BB 4
#define LL 8192
#define HH 64
#define NSTATE 16
#define DBLK 4
#define DCONV 16
#define DINNER 128
#define HEADDIM 16
#define NHEADS 8
#define CONV_DIM 160
#define DPROJ 296
#define QSUB 32
#define NSUB (LL/QSUB)
#define NTOK (BB*LL)

// ---------------- scratch (device globals; no allocation) ----------------
__device__ float g_h[NTOK*HH];
__device__ float g_zx[NTOK*DPROJ];
__device__ float g_xBC[NTOK*CONV_DIM];
__device__ float g_acs[BB*NSUB*NHEADS*QSUB];
__device__ float g_stl[BB*NSUB*NHEADS*256];
__device__ float g_prev[BB*NSUB*NHEADS*256];
__device__ float g_y[NTOK*DINNER];

// ---------------- nop (window shift: capture k_conv this round) ----------------
__global__ void k_nop(){}

// ---------------- embed ----------------
__global__ void k_embed(const float* __restrict__ x, const float* __restrict__ w_in){
    int i = blockIdx.x*blockDim.x + threadIdx.x;
    int tok = i >> 6; int d = i & 63;
    g_h[i] = x[tok] * w_in[d];
}

// ---------------- in_proj: 32 tokens/block, half-K weight staging -> 3 CTAs/SM ----------------
#define WSP2 33
#define INPROJ_SMEM ((32*64 + DPROJ*WSP2)*4)
__global__ void __launch_bounds__(320,3) k_inproj(const float* __restrict__ w){
    extern __shared__ float smp[];
    float* hs = smp;                 // [32][64]
    float* ws = smp + 2048;          // [296][33] (half of K)
    int tid = threadIdx.x;
    int t0 = blockIdx.x*32;
    for (int i=tid; i<32*64; i+=320) hs[i] = g_h[t0*64 + i];
    float acc[32];
    #pragma unroll
    for (int t=0; t<32; t++) acc[t] = 0.f;
    for (int half=0; half<2; half++){
        __syncthreads();   // prior-half compute done before ws restage (and hs ready on 1st pass)
        for (int i=tid; i<DPROJ*32; i+=320){
            int e=i>>5, d=i&31;
            ws[e*WSP2+d] = w[e*64 + half*32 + d];
        }
        __syncthreads();
        if (tid < DPROJ){
            #pragma unroll
            for (int dq=0; dq<4; dq++){
                float wr[8];
                #pragma unroll
                for (int d=0; d<8; d++) wr[d] = ws[tid*WSP2 + dq*8 + d];
                #pragma unroll
                for (int d=0; d<8; d+=4){
                    #pragma unroll
                    for (int t=0; t<32; t++){
                        float4 h4 = *(const float4*)&hs[t*64 + half*32 + dq*8 + d];
                        acc[t] = fmaf(wr[d],   h4.x, acc[t]);
                        acc[t] = fmaf(wr[d+1], h4.y, acc[t]);
                        acc[t] = fmaf(wr[d+2], h4.z, acc[t]);
                        acc[t] = fmaf(wr[d+3], h4.w, acc[t]);
                    }
                }
            }
        }
    }
    if (tid < DPROJ){
        #pragma unroll
        for (int t=0; t<32; t++) g_zx[(size_t)(t0+t)*DPROJ + tid] = acc[t];
    }
}

// ---------------- depthwise causal conv + bias + silu (16 tokens/thread) ----------------
__global__ void __launch_bounds__(256) k_conv(const float* __restrict__ cw, const float* __restrict__ cb){
    __shared__ float cws[CONV_DIM*17];
    __shared__ float cbs[CONV_DIM];
    int tid = threadIdx.x;
    for (int i=tid; i<CONV_DIM*DCONV; i+=256){ int ch=i>>4, k=i&15; cws[ch*17+k] = cw[i]; }
    if (tid < CONV_DIM) cbs[tid] = cb[tid];
    __syncthreads();
    int idx = blockIdx.x*blockDim.x + tid;
    int ch  = idx % CONV_DIM;
    int grp = idx / CONV_DIM;
    int tok0 = grp*16;
    int b = tok0 / LL, l0 = tok0 % LL;
    float wv[DCONV];
    #pragma unroll
    for (int k=0; k<DCONV; k++) wv[k] = cws[ch*17 + k];
    float in[DCONV+15];
    #pragma unroll
    for (int k=0; k<DCONV+15; k++){
        int ls = l0 - (DCONV-1) + k;
        in[k] = (ls >= 0) ? g_zx[(size_t)(b*LL + ls)*DPROJ + DINNER + ch] : 0.f;
    }
    float bias = cbs[ch];
    #pragma unroll
    for (int j=0; j<16; j++){
        float acc = bias;
        #pragma unroll
        for (int k=0; k<DCONV; k++) acc = fmaf(wv[k], in[j+k], acc);
        g_xBC[(size_t)(tok0+j)*CONV_DIM + ch] = acc / (1.f + __expf(-acc));
    }
}

// ---------------- intra-subchunk (Q=32): R8 version (best measured: 54.7us) ----------------
__global__ void __launch_bounds__(256) k_intra(const float* __restrict__ dtb,
                                               const float* __restrict__ alog,
                                               const float* __restrict__ dskip){
    int blk = blockIdx.x;
    int hp = blk & 3;
    int grp = blk >> 2;
    int b = grp >> 6, g = grp & 63;
    int tokbase = b*LL + g*128;
    int tid = threadIdx.x;
    int hl = tid >> 7;
    int l  = tid & 127;
    int lane = tid & 31;
    int h = hp*2 + hl;
    __shared__ float Bs[128*16];
    __shared__ float Cs[128*16];
    __shared__ float Xs[2][128*16];
    __shared__ float2 ps[2][128];
    __shared__ float dd[2][128];

    float vraw = g_zx[(size_t)(tokbase+l)*DPROJ + DINNER + CONV_DIM + h] + dtb[h];
    float dt = (vraw > 20.f) ? vraw : log1pf(__expf(vraw));
    float sc = dt * (-__expf(alog[h]));
    #pragma unroll
    for (int off=1; off<32; off<<=1){
        float u = __shfl_up_sync(0xffffffffu, sc, off);
        if (lane >= off) sc += u;
    }
    float tot = __shfl_sync(0xffffffffu, sc, 31);
    ps[hl][l] = make_float2(sc, dt);
    dd[hl][l] = __expf(tot - sc) * dt;
    int gsub = b*NSUB + g*4 + (l>>5);
    g_acs[(gsub*NHEADS + h)*QSUB + lane] = sc;

    {
        const float* row = &g_xBC[(size_t)(tokbase+l)*CONV_DIM];
        if (hl == 0){
            #pragma unroll
            for (int k=0;k<4;k++) *(float4*)&Bs[l*16+4*k] = *(const float4*)&row[DINNER+4*k];
        } else {
            #pragma unroll
            for (int k=0;k<4;k++) *(float4*)&Cs[l*16+4*k] = *(const float4*)&row[DINNER+NSTATE+4*k];
        }
        #pragma unroll
        for (int k=0;k<4;k++) *(float4*)&Xs[hl][l*16+4*k] = *(const float4*)&row[h*HEADDIM+4*k];
    }
    __syncthreads();

    {
        int hh = tid>>7, q=(tid>>5)&3, n=(tid>>1)&15, ph=tid&1;
        const float* Xq = Xs[hh];
        float a0=0,a1=0,a2=0,a3=0,a4=0,a5=0,a6=0,a7=0;
        int l0 = q*32;
        #pragma unroll 4
        for (int ll=0; ll<32; ll++){
            int lr = l0+ll;
            float bd = Bs[lr*16+n]*dd[hh][lr];
            float4 xa = *(const float4*)&Xq[lr*16+ph*8];
            float4 xb = *(const float4*)&Xq[lr*16+ph*8+4];
            a0=fmaf(bd,xa.x,a0); a1=fmaf(bd,xa.y,a1); a2=fmaf(bd,xa.z,a2); a3=fmaf(bd,xa.w,a3);
            a4=fmaf(bd,xb.x,a4); a5=fmaf(bd,xb.y,a5); a6=fmaf(bd,xb.z,a6); a7=fmaf(bd,xb.w,a7);
        }
        int base = ((b*NSUB + g*4 + q)*NHEADS + hp*2+hh)*256 + n*16 + ph*8;
        *(float4*)&g_stl[base]   = make_float4(a0,a1,a2,a3);
        *(float4*)&g_stl[base+4] = make_float4(a4,a5,a6,a7);
    }

    {
        const float* Xsh = Xs[hl];
        float4 c0 = *(const float4*)&Cs[l*16+0];
        float4 c1 = *(const float4*)&Cs[l*16+4];
        float4 c2 = *(const float4*)&Cs[l*16+8];
        float4 c3 = *(const float4*)&Cs[l*16+12];
        float al = sc;
        float dsk = dskip[h];
        float4 y0 = *(const float4*)&Xsh[l*16+0];
        float4 y1 = *(const float4*)&Xsh[l*16+4];
        float4 y2 = *(const float4*)&Xsh[l*16+8];
        float4 y3 = *(const float4*)&Xsh[l*16+12];
        y0.x*=dsk; y0.y*=dsk; y0.z*=dsk; y0.w*=dsk;
        y1.x*=dsk; y1.y*=dsk; y1.z*=dsk; y1.w*=dsk;
        y2.x*=dsk; y2.y*=dsk; y2.z*=dsk; y2.w*=dsk;
        y3.x*=dsk; y3.y*=dsk; y3.z*=dsk; y3.w*=dsk;
        int s0 = l & ~31;
        for (int s=s0; s<=l; s++){
            float2 pd = ps[hl][s];
            float4 b0 = *(const float4*)&Bs[s*16+0];
            float4 b1 = *(const float4*)&Bs[s*16+4];
            float4 b2 = *(const float4*)&Bs[s*16+8];
            float4 b3 = *(const float4*)&Bs[s*16+12];
            float p0 = fmaf(c0.x,b0.x, c0.y*b0.y); p0 = fmaf(c0.z,b0.z,p0); p0 = fmaf(c0.w,b0.w,p0);
            float p1 = fmaf(c1.x,b1.x, c1.y*b1.y); p1 = fmaf(c1.z,b1.z,p1); p1 = fmaf(c1.w,b1.w,p1);
            float p2 = fmaf(c2.x,b2.x, c2.y*b2.y); p2 = fmaf(c2.z,b2.z,p2); p2 = fmaf(c2.w,b2.w,p2);
            float p3 = fmaf(c3.x,b3.x, c3.y*b3.y); p3 = fmaf(c3.z,b3.z,p3); p3 = fmaf(c3.w,b3.w,p3);
            float dot = (p0+p1) + (p2+p3);
            float wgt = dot * (__expf(al - pd.x) * pd.y);
            float4 x0 = *(const float4*)&Xsh[s*16+0];
            float4 x1 = *(const float4*)&Xsh[s*16+4];
            float4 x2 = *(const float4*)&Xsh[s*16+8];
            float4 x3 = *(const float4*)&Xsh[s*16+12];
            y0.x = fmaf(wgt,x0.x,y0.x); y0.y = fmaf(wgt,x0.y,y0.y); y0.z = fmaf(wgt,x0.z,y0.z); y0.w = fmaf(wgt,x0.w,y0.w);
            y1.x = fmaf(wgt,x1.x,y1.x); y1.y = fmaf(wgt,x1.y,y1.y); y1.z = fmaf(wgt,x1.z,y1.z); y1.w = fmaf(wgt,x1.w,y1.w);
            y2.x = fmaf(wgt,x2.x,y2.x); y2.y = fmaf(wgt,x2.y,y2.y); y2.z = fmaf(wgt,x2.z,y2.z); y2.w = fmaf(wgt,x2.w,y2.w);
            y3.x = fmaf(wgt,x3.x,y3.x); y3.y = fmaf(wgt,x3.y,y3.y); y3.z = fmaf(wgt,x3.z,y3.z); y3.w = fmaf(wgt,x3.w,y3.w);
        }
        float* yo = &g_y[(size_t)(tokbase+l)*DINNER + h*HEADDIM];
        *(float4*)&yo[0]  = y0;
        *(float4*)&yo[4]  = y1;
        *(float4*)&yo[8]  = y2;
        *(float4*)&yo[12] = y3;
    }
}

// ---------------- inter-subchunk scan ----------------
__global__ void k_scan(const float* __restrict__ ist){
    int b = blockIdx.x>>3, h = blockIdx.x&7;
    int tid = threadIdx.x;
    __shared__ float ats[NSUB];
    ats[tid] = __expf(g_acs[((b*NSUB + tid)*NHEADS + h)*QSUB + QSUB-1]);
    __syncthreads();
    float S = ist[h*256 + (tid&15)*16 + (tid>>4)];
    size_t idx0 = ((size_t)(b*NSUB)*NHEADS + h)*256 + tid;
    const size_t stride = (size_t)NHEADS*256;
    for (int c0=0; c0<NSUB; c0+=16){
        float buf[16];
        #pragma unroll
        for (int j=0; j<16; j++) buf[j] = g_stl[idx0 + (size_t)(c0+j)*stride];
        #pragma unroll
        for (int j=0; j<16; j++){
            g_prev[idx0 + (size_t)(c0+j)*stride] = S;
            S = fmaf(S, ats[c0+j], buf[j]);
        }
    }
}

// ---------------- Y_off + gate + RMSnorm + out_proj + softsign + MLP + residual ----------------
#define KP 68
#define SMEM_OUT_FLOATS 27648
__global__ void __launch_bounds__(512,2) k_out(const float* __restrict__ nw,
                                               const float* __restrict__ ow,
                                               const float* __restrict__ mw,
                                               const float* __restrict__ mb){
    extern __shared__ float sm[];
    float* ysH  = sm;              // phase1 pass: [32][132]
    float* zsH  = sm + 4224;       // phase1 pass: [32][132]
    float* wT1  = sm;              // phase2 overlay: [128][KP]
    float* ynT  = sm + 8704;       // [128][KP]
    float* prevs= sm + 17408;      // [16][260] plain [n][p]
    float* cmr  = sm + 21568;      // [64][16]
    float* ear  = sm + 22592;      // [64][8]
    float* nws  = sm + 23104;      // 128
    float* mbs  = sm + 23232;      // 64
    float* wT2  = sm + 17408;      // phase2 overlay of prevs: [64][KP]
    float* tT   = sm + 23296;      // [64][KP]
    int tid = threadIdx.x;
    int tok0 = blockIdx.x*64;
    int b = tok0 >> 13;
    int lbase = tok0 & (LL-1);
    int sub0 = b*NSUB + (lbase>>5);

    for (int i=tid; i<4096; i+=512){
        int sl=i>>11, r=i&2047, hh=r>>8, el=r&255;
        prevs[(sl*8+hh)*260 + el] = g_prev[((size_t)(sub0+sl)*NHEADS+hh)*256 + el];
    }
    for (int i=tid; i<1024; i+=512){ int t=i>>4, n=i&15;
        cmr[i] = g_xBC[(size_t)(tok0+t)*CONV_DIM + DINNER + NSTATE + n]; }
    if (tid < 512){ int t=tid>>3, hh=tid&7;
        ear[tid] = __expf(g_acs[((size_t)(sub0 + (t>>5))*NHEADS + hh)*QSUB + (t&31)]); }
    if (tid < 128) nws[tid] = nw[tid];
    if (tid < 64)  mbs[tid] = mb[tid];

    for (int pass=0; pass<2; pass++){
        __syncthreads();
        for (int i=tid; i<1024; i+=512){
            int t = i>>5, c4 = i&31;
            *(float4*)&ysH[t*132 + c4*4] = *(const float4*)&g_y[(size_t)(tok0+pass*32+t)*DINNER + c4*4];
            *(float4*)&zsH[t*132 + c4*4] = *(const float4*)&g_zx[(size_t)(tok0+pass*32+t)*DPROJ + c4*4];
        }
        __syncthreads();
        {
            int tokL = tid>>4, sub = tid&15;
            int tok = pass*32 + tokL;
            int h = sub>>1, p0 = (sub&1)*8;
            float cm[16];
            #pragma unroll
            for (int n=0; n<16; n++) cm[n] = cmr[tok*16+n];
            const float* pv = &prevs[(pass*8+h)*260];
            float4 acc0 = make_float4(0.f,0.f,0.f,0.f);
            float4 acc1 = make_float4(0.f,0.f,0.f,0.f);
            #pragma unroll
            for (int n=0; n<16; n++){
                float4 a = *(const float4*)&pv[n*16+p0];
                float4 c = *(const float4*)&pv[n*16+p0+4];
                acc0.x = fmaf(cm[n], a.x, acc0.x); acc0.y = fmaf(cm[n], a.y, acc0.y);
                acc0.z = fmaf(cm[n], a.z, acc0.z); acc0.w = fmaf(cm[n], a.w, acc0.w);
                acc1.x = fmaf(cm[n], c.x, acc1.x); acc1.y = fmaf(cm[n], c.y, acc1.y);
                acc1.z = fmaf(cm[n], c.z, acc1.z); acc1.w = fmaf(cm[n], c.w, acc1.w);
            }
            float e_a = ear[tok*8+h];
            float av[8] = {acc0.x,acc0.y,acc0.z,acc0.w, acc1.x,acc1.y,acc1.z,acc1.w};
            float yv[8]; float ss = 0.f;
            #pragma unroll
            for (int j=0; j<8; j++){
                int ch = sub*8 + j;
                float y = ysH[tokL*132+ch] + e_a*av[j];
                float z = zsH[tokL*132+ch];
                y *= z / (1.f + __expf(-z));
                yv[j] = y; ss = fmaf(y, y, ss);
            }
            ss += __shfl_xor_sync(0xffffffffu, ss, 1, 16);
            ss += __shfl_xor_sync(0xffffffffu, ss, 2, 16);
            ss += __shfl_xor_sync(0xffffffffu, ss, 4, 16);
            ss += __shfl_xor_sync(0xffffffffu, ss, 8, 16);
            float scale = rsqrtf(ss*(1.f/128.f) + 1e-5f);
            #pragma unroll
            for (int j=0; j<8; j++){
                int ch = sub*8 + j;
                ynT[ch*KP + tok] = yv[j]*scale*nws[ch];
            }
        }
    }
    __syncthreads();

    for (int i=tid; i<128*64; i+=512){ int d=i>>7, e=i&127; wT1[e*KP+d] = ow[i]; }
    for (int i=tid; i<64*64;  i+=512){ int d=i>>6, e=i&63;  wT2[e*KP+d] = mw[i]; }
    __syncthreads();

    {
        int i = tid>>4, j = tid&15;
        float a00=0,a01=0,a02=0,a03=0, a10=0,a11=0,a12=0,a13=0;
        #pragma unroll 8
        for (int e=0; e<128; e++){
            float2 yv2 = *(const float2*)&ynT[e*KP + i*2];
            float4 wv4 = *(const float4*)&wT1[e*KP + j*4];
            a00=fmaf(yv2.x,wv4.x,a00); a01=fmaf(yv2.x,wv4.y,a01); a02=fmaf(yv2.x,wv4.z,a02); a03=fmaf(yv2.x,wv4.w,a03);
            a10=fmaf(yv2.y,wv4.x,a10); a11=fmaf(yv2.y,wv4.y,a11); a12=fmaf(yv2.y,wv4.z,a12); a13=fmaf(yv2.y,wv4.w,a13);
        }
        #define SS(v) ((v)*rsqrtf(1.f+(v)*(v)))
        tT[(j*4+0)*KP + i*2+0]=SS(a00); tT[(j*4+1)*KP + i*2+0]=SS(a01); tT[(j*4+2)*KP + i*2+0]=SS(a02); tT[(j*4+3)*KP + i*2+0]=SS(a03);
        tT[(j*4+0)*KP + i*2+1]=SS(a10); tT[(j*4+1)*KP + i*2+1]=SS(a11); tT[(j*4+2)*KP + i*2+1]=SS(a12); tT[(j*4+3)*KP + i*2+1]=SS(a13);
        #undef SS
    }
    __syncthreads();

    {
        int i = tid>>4, j = tid&15;
        float4 mbv = *(const float4*)&mbs[j*4];
        float a00=mbv.x,a01=mbv.y,a02=mbv.z,a03=mbv.w;
        float a10=mbv.x,a11=mbv.y,a12=mbv.z,a13=mbv.w;
        #pragma unroll 8
        for (int e=0; e<64; e++){
            float2 tv2 = *(const float2*)&tT[e*KP + i*2];
            float4 wv4 = *(const float4*)&wT2[e*KP + j*4];
            a00=fmaf(tv2.x,wv4.x,a00); a01=fmaf(tv2.x,wv4.y,a01); a02=fmaf(tv2.x,wv4.z,a02); a03=fmaf(tv2.x,wv4.w,a03);
            a10=fmaf(tv2.y,wv4.x,a10); a11=fmaf(tv2.y,wv4.y,a11); a12=fmaf(tv2.y,wv4.z,a12); a13=fmaf(tv2.y,wv4.w,a13);
        }
        int gt0 = tok0 + i*2;
        float4 h0 = *(const float4*)&g_h[(size_t)(gt0+0)*HH + j*4];
        float4 h1 = *(const float4*)&g_h[(size_t)(gt0+1)*HH + j*4];
        h0.x+=a00; h0.y+=a01; h0.z+=a02; h0.w+=a03;
        h1.x+=a10; h1.y+=a11; h1.z+=a12; h1.w+=a13;
        *(float4*)&g_h[(size_t)(gt0+0)*HH + j*4] = h0;
        *(float4*)&g_h[(size_t)(gt0+1)*HH + j*4] = h1;
    }
}

// ---------------- final ----------------
__global__ void k_final(const float* __restrict__ wo, float* __restrict__ out){
    int tid = threadIdx.x;
    int tok = blockIdx.x*8 + (tid>>5); int lane = tid&31;
    float v = g_h[tok*HH + lane]*wo[lane] + g_h[tok*HH + lane + 32]*wo[lane+32];
    #pragma unroll
    for (int o=16; o; o>>=1) v += __shfl_xor_sync(~0u, v, o);
    if (lane == 0) out[tok] = v;
}

extern "C" void kernel_launch(void* const* d_in, const int* in_sizes, int n_in,
                              void* d_out, int out_size){
    const float* x    = (const float*)d_in[0];
    const float* w_in = (const float*)d_in[1];
    const float* w_out= (const float*)d_in[2];
    const float* ipw  = (const float*)d_in[3];
    const float* cw   = (const float*)d_in[4];
    const float* cb   = (const float*)d_in[5];
    const float* dtb  = (const float*)d_in[6];
    const float* alog = (const float*)d_in[7];
    const float* dsk  = (const float*)d_in[8];
    const float* ist  = (const float*)d_in[9];
    const float* nw   = (const float*)d_in[10];
    const float* opw  = (const float*)d_in[11];
    const float* mw   = (const float*)d_in[12];
    const float* mb   = (const float*)d_in[13];
    float* out = (float*)d_out;

    cudaFuncSetAttribute(k_out, cudaFuncAttributeMaxDynamicSharedMemorySize,
                         SMEM_OUT_FLOATS*4);
    cudaFuncSetAttribute(k_inproj, cudaFuncAttributeMaxDynamicSharedMemorySize,
                         INPROJ_SMEM);

    k_nop<<<1,1>>>();
    k_embed<<<NTOK*HH/256, 256>>>(x, w_in);
    for (int i=0; i<DBLK; i++){
        k_inproj<<<NTOK/32, 320, INPROJ_SMEM>>>(ipw + (size_t)i*DPROJ*HH);
        k_conv<<<(NTOK/16)*CONV_DIM/256, 256>>>(cw + i*CONV_DIM*DCONV, cb + i*CONV_DIM);
        k_intra<<<BB*64*4, 256>>>(dtb + i*NHEADS, alog + i*NHEADS, dsk + i*NHEADS);
        k_scan<<<BB*NHEADS, 256>>>(ist + (size_t)i*NHEADS*HEADDIM*NSTATE);
        k_out<<<NTOK/64, 512, SMEM_OUT_FLOATS*4>>>(nw + i*DINNER,
                                                   opw + (size_t)i*HH*DINNER,
                                                   mw + i*HH*HH, mb + i*HH);
    }
    k_final<<<NTOK/8, 256>>>(w_out, out);
}

// round 14
// speedup vs baseline: 1.0308x; 1.0308x over previous
#include <cuda_runtime.h>
#include <math.h>

#define BB 4
#define LL 8192
#define HH 64
#define NSTATE 16
#define DBLK 4
#define DCONV 16
#define DINNER 128
#define HEADDIM 16
#define NHEADS 8
#define CONV_DIM 160
#define DPROJ 296
#define QSUB 32
#define NSUB (LL/QSUB)
#define NTOK (BB*LL)

// ---------------- scratch (device globals; no allocation) ----------------
__device__ float g_h[NTOK*HH];
__device__ float g_zx[NTOK*DPROJ];
__device__ float g_xBC[NTOK*CONV_DIM];
__device__ float g_acs[BB*NSUB*NHEADS*QSUB];
__device__ float g_stl[BB*NSUB*NHEADS*256];
__device__ float g_prev[BB*NSUB*NHEADS*256];
__device__ float g_y[NTOK*DINNER];

// ---------------- nop (window shift: capture k_inproj this round) ----------------
__global__ void k_nop(){}

// ---------------- embed ----------------
__global__ void k_embed(const float* __restrict__ x, const float* __restrict__ w_in){
    int i = blockIdx.x*blockDim.x + threadIdx.x;
    int tok = i >> 6; int d = i & 63;
    g_h[i] = x[tok] * w_in[d];
}

// ---------------- in_proj: 32 tokens/block, packed f32x2 FMA (FFMA2) ----------------
#define WSP 67
#define HTP 36
#define INPROJ_SMEM ((64*HTP + DPROJ*WSP)*4)
__global__ void __launch_bounds__(320) k_inproj(const float* __restrict__ w){
    extern __shared__ float smp[];
    float* hs_t = smp;               // [64 d][HTP] transposed h tile
    float* ws   = smp + 64*HTP;      // [296][WSP]
    int tid = threadIdx.x;
    int t0 = blockIdx.x*32;
    for (int i=tid; i<2048; i+=320){ int t=i>>6, d=i&63; hs_t[d*HTP+t] = g_h[(size_t)t0*64 + i]; }
    for (int i=tid; i<DPROJ*64; i+=320){ int e=i>>6, d=i&63; ws[e*WSP+d] = w[i]; }
    __syncthreads();
    if (tid >= DPROJ) return;
    unsigned long long acc[16];
    #pragma unroll
    for (int t=0; t<16; t++) acc[t] = 0ULL;
    #pragma unroll 4
    for (int d=0; d<64; d++){
        float wv = ws[tid*WSP + d];
        unsigned long long w2;
        asm("mov.b64 %0, {%1, %1};" : "=l"(w2) : "r"(__float_as_uint(wv)));
        const ulonglong2* hp = (const ulonglong2*)&hs_t[d*HTP];
        #pragma unroll
        for (int t=0; t<8; t++){
            ulonglong2 hh = hp[t];
            asm("fma.rn.f32x2 %0, %1, %2, %0;" : "+l"(acc[2*t])   : "l"(hh.x), "l"(w2));
            asm("fma.rn.f32x2 %0, %1, %2, %0;" : "+l"(acc[2*t+1]) : "l"(hh.y), "l"(w2));
        }
    }
    #pragma unroll
    for (int t=0; t<16; t++){
        float2 v = *(float2*)&acc[t];
        g_zx[(size_t)(t0+2*t  )*DPROJ + tid] = v.x;
        g_zx[(size_t)(t0+2*t+1)*DPROJ + tid] = v.y;
    }
}

// ---------------- depthwise causal conv + bias + silu (16 tokens/thread) ----------------
__global__ void __launch_bounds__(256) k_conv(const float* __restrict__ cw, const float* __restrict__ cb){
    __shared__ float cws[CONV_DIM*17];
    __shared__ float cbs[CONV_DIM];
    int tid = threadIdx.x;
    for (int i=tid; i<CONV_DIM*DCONV; i+=256){ int ch=i>>4, k=i&15; cws[ch*17+k] = cw[i]; }
    if (tid < CONV_DIM) cbs[tid] = cb[tid];
    __syncthreads();
    int idx = blockIdx.x*blockDim.x + tid;
    int ch  = idx % CONV_DIM;
    int grp = idx / CONV_DIM;
    int tok0 = grp*16;
    int b = tok0 / LL, l0 = tok0 % LL;
    float wv[DCONV];
    #pragma unroll
    for (int k=0; k<DCONV; k++) wv[k] = cws[ch*17 + k];
    float in[DCONV+15];
    #pragma unroll
    for (int k=0; k<DCONV+15; k++){
        int ls = l0 - (DCONV-1) + k;
        in[k] = (ls >= 0) ? g_zx[(size_t)(b*LL + ls)*DPROJ + DINNER + ch] : 0.f;
    }
    float bias = cbs[ch];
    #pragma unroll
    for (int j=0; j<16; j++){
        float acc = bias;
        #pragma unroll
        for (int k=0; k<DCONV; k++) acc = fmaf(wv[k], in[j+k], acc);
        g_xBC[(size_t)(tok0+j)*CONV_DIM + ch] = acc / (1.f + __expf(-acc));
    }
}

// ---------------- intra-subchunk (Q=32): R8 version (best measured: 54.7us) ----------------
__global__ void __launch_bounds__(256) k_intra(const float* __restrict__ dtb,
                                               const float* __restrict__ alog,
                                               const float* __restrict__ dskip){
    int blk = blockIdx.x;
    int hp = blk & 3;
    int grp = blk >> 2;
    int b = grp >> 6, g = grp & 63;
    int tokbase = b*LL + g*128;
    int tid = threadIdx.x;
    int hl = tid >> 7;
    int l  = tid & 127;
    int lane = tid & 31;
    int h = hp*2 + hl;
    __shared__ float Bs[128*16];
    __shared__ float Cs[128*16];
    __shared__ float Xs[2][128*16];
    __shared__ float2 ps[2][128];
    __shared__ float dd[2][128];

    float vraw = g_zx[(size_t)(tokbase+l)*DPROJ + DINNER + CONV_DIM + h] + dtb[h];
    float dt = (vraw > 20.f) ? vraw : log1pf(__expf(vraw));
    float sc = dt * (-__expf(alog[h]));
    #pragma unroll
    for (int off=1; off<32; off<<=1){
        float u = __shfl_up_sync(0xffffffffu, sc, off);
        if (lane >= off) sc += u;
    }
    float tot = __shfl_sync(0xffffffffu, sc, 31);
    ps[hl][l] = make_float2(sc, dt);
    dd[hl][l] = __expf(tot - sc) * dt;
    int gsub = b*NSUB + g*4 + (l>>5);
    g_acs[(gsub*NHEADS + h)*QSUB + lane] = sc;

    {
        const float* row = &g_xBC[(size_t)(tokbase+l)*CONV_DIM];
        if (hl == 0){
            #pragma unroll
            for (int k=0;k<4;k++) *(float4*)&Bs[l*16+4*k] = *(const float4*)&row[DINNER+4*k];
        } else {
            #pragma unroll
            for (int k=0;k<4;k++) *(float4*)&Cs[l*16+4*k] = *(const float4*)&row[DINNER+NSTATE+4*k];
        }
        #pragma unroll
        for (int k=0;k<4;k++) *(float4*)&Xs[hl][l*16+4*k] = *(const float4*)&row[h*HEADDIM+4*k];
    }
    __syncthreads();

    {
        int hh = tid>>7, q=(tid>>5)&3, n=(tid>>1)&15, ph=tid&1;
        const float* Xq = Xs[hh];
        float a0=0,a1=0,a2=0,a3=0,a4=0,a5=0,a6=0,a7=0;
        int l0 = q*32;
        #pragma unroll 4
        for (int ll=0; ll<32; ll++){
            int lr = l0+ll;
            float bd = Bs[lr*16+n]*dd[hh][lr];
            float4 xa = *(const float4*)&Xq[lr*16+ph*8];
            float4 xb = *(const float4*)&Xq[lr*16+ph*8+4];
            a0=fmaf(bd,xa.x,a0); a1=fmaf(bd,xa.y,a1); a2=fmaf(bd,xa.z,a2); a3=fmaf(bd,xa.w,a3);
            a4=fmaf(bd,xb.x,a4); a5=fmaf(bd,xb.y,a5); a6=fmaf(bd,xb.z,a6); a7=fmaf(bd,xb.w,a7);
        }
        int base = ((b*NSUB + g*4 + q)*NHEADS + hp*2+hh)*256 + n*16 + ph*8;
        *(float4*)&g_stl[base]   = make_float4(a0,a1,a2,a3);
        *(float4*)&g_stl[base+4] = make_float4(a4,a5,a6,a7);
    }

    {
        const float* Xsh = Xs[hl];
        float4 c0 = *(const float4*)&Cs[l*16+0];
        float4 c1 = *(const float4*)&Cs[l*16+4];
        float4 c2 = *(const float4*)&Cs[l*16+8];
        float4 c3 = *(const float4*)&Cs[l*16+12];
        float al = sc;
        float dsk = dskip[h];
        float4 y0 = *(const float4*)&Xsh[l*16+0];
        float4 y1 = *(const float4*)&Xsh[l*16+4];
        float4 y2 = *(const float4*)&Xsh[l*16+8];
        float4 y3 = *(const float4*)&Xsh[l*16+12];
        y0.x*=dsk; y0.y*=dsk; y0.z*=dsk; y0.w*=dsk;
        y1.x*=dsk; y1.y*=dsk; y1.z*=dsk; y1.w*=dsk;
        y2.x*=dsk; y2.y*=dsk; y2.z*=dsk; y2.w*=dsk;
        y3.x*=dsk; y3.y*=dsk; y3.z*=dsk; y3.w*=dsk;
        int s0 = l & ~31;
        for (int s=s0; s<=l; s++){
            float2 pd = ps[hl][s];
            float4 b0 = *(const float4*)&Bs[s*16+0];
            float4 b1 = *(const float4*)&Bs[s*16+4];
            float4 b2 = *(const float4*)&Bs[s*16+8];
            float4 b3 = *(const float4*)&Bs[s*16+12];
            float p0 = fmaf(c0.x,b0.x, c0.y*b0.y); p0 = fmaf(c0.z,b0.z,p0); p0 = fmaf(c0.w,b0.w,p0);
            float p1 = fmaf(c1.x,b1.x, c1.y*b1.y); p1 = fmaf(c1.z,b1.z,p1); p1 = fmaf(c1.w,b1.w,p1);
            float p2 = fmaf(c2.x,b2.x, c2.y*b2.y); p2 = fmaf(c2.z,b2.z,p2); p2 = fmaf(c2.w,b2.w,p2);
            float p3 = fmaf(c3.x,b3.x, c3.y*b3.y); p3 = fmaf(c3.z,b3.z,p3); p3 = fmaf(c3.w,b3.w,p3);
            float dot = (p0+p1) + (p2+p3);
            float wgt = dot * (__expf(al - pd.x) * pd.y);
            float4 x0 = *(const float4*)&Xsh[s*16+0];
            float4 x1 = *(const float4*)&Xsh[s*16+4];
            float4 x2 = *(const float4*)&Xsh[s*16+8];
            float4 x3 = *(const float4*)&Xsh[s*16+12];
            y0.x = fmaf(wgt,x0.x,y0.x); y0.y = fmaf(wgt,x0.y,y0.y); y0.z = fmaf(wgt,x0.z,y0.z); y0.w = fmaf(wgt,x0.w,y0.w);
            y1.x = fmaf(wgt,x1.x,y1.x); y1.y = fmaf(wgt,x1.y,y1.y); y1.z = fmaf(wgt,x1.z,y1.z); y1.w = fmaf(wgt,x1.w,y1.w);
            y2.x = fmaf(wgt,x2.x,y2.x); y2.y = fmaf(wgt,x2.y,y2.y); y2.z = fmaf(wgt,x2.z,y2.z); y2.w = fmaf(wgt,x2.w,y2.w);
            y3.x = fmaf(wgt,x3.x,y3.x); y3.y = fmaf(wgt,x3.y,y3.y); y3.z = fmaf(wgt,x3.z,y3.z); y3.w = fmaf(wgt,x3.w,y3.w);
        }
        float* yo = &g_y[(size_t)(tokbase+l)*DINNER + h*HEADDIM];
        *(float4*)&yo[0]  = y0;
        *(float4*)&yo[4]  = y1;
        *(float4*)&yo[8]  = y2;
        *(float4*)&yo[12] = y3;
    }
}

// ---------------- inter-subchunk scan ----------------
__global__ void k_scan(const float* __restrict__ ist){
    int b = blockIdx.x>>3, h = blockIdx.x&7;
    int tid = threadIdx.x;
    __shared__ float ats[NSUB];
    ats[tid] = __expf(g_acs[((b*NSUB + tid)*NHEADS + h)*QSUB + QSUB-1]);
    __syncthreads();
    float S = ist[h*256 + (tid&15)*16 + (tid>>4)];
    size_t idx0 = ((size_t)(b*NSUB)*NHEADS + h)*256 + tid;
    const size_t stride = (size_t)NHEADS*256;
    for (int c0=0; c0<NSUB; c0+=16){
        float buf[16];
        #pragma unroll
        for (int j=0; j<16; j++) buf[j] = g_stl[idx0 + (size_t)(c0+j)*stride];
        #pragma unroll
        for (int j=0; j<16; j++){
            g_prev[idx0 + (size_t)(c0+j)*stride] = S;
            S = fmaf(S, ats[c0+j], buf[j]);
        }
    }
}

// ---------------- Y_off + gate + RMSnorm + out_proj + softsign + MLP + residual ----------------
#define KP 68
#define SMEM_OUT_FLOATS 27648
__global__ void __launch_bounds__(512,2) k_out(const float* __restrict__ nw,
                                               const float* __restrict__ ow,
                                               const float* __restrict__ mw,
                                               const float* __restrict__ mb){
    extern __shared__ float sm[];
    float* ysH  = sm;              // phase1 pass: [32][132]
    float* zsH  = sm + 4224;       // phase1 pass: [32][132]
    float* wT1  = sm;              // phase2 overlay: [128][KP]
    float* ynT  = sm + 8704;       // [128][KP]
    float* prevs= sm + 17408;      // [16][260] plain [n][p]
    float* cmr  = sm + 21568;      // [64][16]
    float* ear  = sm + 22592;      // [64][8]
    float* nws  = sm + 23104;      // 128
    float* mbs  = sm + 23232;      // 64
    float* wT2  = sm + 17408;      // phase2 overlay of prevs: [64][KP]
    float* tT   = sm + 23296;      // [64][KP]
    int tid = threadIdx.x;
    int tok0 = blockIdx.x*64;
    int b = tok0 >> 13;
    int lbase = tok0 & (LL-1);
    int sub0 = b*NSUB + (lbase>>5);

    for (int i=tid; i<4096; i+=512){
        int sl=i>>11, r=i&2047, hh=r>>8, el=r&255;
        prevs[(sl*8+hh)*260 + el] = g_prev[((size_t)(sub0+sl)*NHEADS+hh)*256 + el];
    }
    for (int i=tid; i<1024; i+=512){ int t=i>>4, n=i&15;
        cmr[i] = g_xBC[(size_t)(tok0+t)*CONV_DIM + DINNER + NSTATE + n]; }
    if (tid < 512){ int t=tid>>3, hh=tid&7;
        ear[tid] = __expf(g_acs[((size_t)(sub0 + (t>>5))*NHEADS + hh)*QSUB + (t&31)]); }
    if (tid < 128) nws[tid] = nw[tid];
    if (tid < 64)  mbs[tid] = mb[tid];

    for (int pass=0; pass<2; pass++){
        __syncthreads();
        for (int i=tid; i<1024; i+=512){
            int t = i>>5, c4 = i&31;
            *(float4*)&ysH[t*132 + c4*4] = *(const float4*)&g_y[(size_t)(tok0+pass*32+t)*DINNER + c4*4];
            *(float4*)&zsH[t*132 + c4*4] = *(const float4*)&g_zx[(size_t)(tok0+pass*32+t)*DPROJ + c4*4];
        }
        __syncthreads();
        {
            int tokL = tid>>4, sub = tid&15;
            int tok = pass*32 + tokL;
            int h = sub>>1, p0 = (sub&1)*8;
            float cm[16];
            #pragma unroll
            for (int n=0; n<16; n++) cm[n] = cmr[tok*16+n];
            const float* pv = &prevs[(pass*8+h)*260];
            float4 acc0 = make_float4(0.f,0.f,0.f,0.f);
            float4 acc1 = make_float4(0.f,0.f,0.f,0.f);
            #pragma unroll
            for (int n=0; n<16; n++){
                float4 a = *(const float4*)&pv[n*16+p0];
                float4 c = *(const float4*)&pv[n*16+p0+4];
                acc0.x = fmaf(cm[n], a.x, acc0.x); acc0.y = fmaf(cm[n], a.y, acc0.y);
                acc0.z = fmaf(cm[n], a.z, acc0.z); acc0.w = fmaf(cm[n], a.w, acc0.w);
                acc1.x = fmaf(cm[n], c.x, acc1.x); acc1.y = fmaf(cm[n], c.y, acc1.y);
                acc1.z = fmaf(cm[n], c.z, acc1.z); acc1.w = fmaf(cm[n], c.w, acc1.w);
            }
            float e_a = ear[tok*8+h];
            float av[8] = {acc0.x,acc0.y,acc0.z,acc0.w, acc1.x,acc1.y,acc1.z,acc1.w};
            float yv[8]; float ss = 0.f;
            #pragma unroll
            for (int j=0; j<8; j++){
                int ch = sub*8 + j;
                float y = ysH[tokL*132+ch] + e_a*av[j];
                float z = zsH[tokL*132+ch];
                y *= z / (1.f + __expf(-z));
                yv[j] = y; ss = fmaf(y, y, ss);
            }
            ss += __shfl_xor_sync(0xffffffffu, ss, 1, 16);
            ss += __shfl_xor_sync(0xffffffffu, ss, 2, 16);
            ss += __shfl_xor_sync(0xffffffffu, ss, 4, 16);
            ss += __shfl_xor_sync(0xffffffffu, ss, 8, 16);
            float scale = rsqrtf(ss*(1.f/128.f) + 1e-5f);
            #pragma unroll
            for (int j=0; j<8; j++){
                int ch = sub*8 + j;
                ynT[ch*KP + tok] = yv[j]*scale*nws[ch];
            }
        }
    }
    __syncthreads();

    for (int i=tid; i<128*64; i+=512){ int d=i>>7, e=i&127; wT1[e*KP+d] = ow[i]; }
    for (int i=tid; i<64*64;  i+=512){ int d=i>>6, e=i&63;  wT2[e*KP+d] = mw[i]; }
    __syncthreads();

    {
        int i = tid>>4, j = tid&15;
        float a00=0,a01=0,a02=0,a03=0, a10=0,a11=0,a12=0,a13=0;
        #pragma unroll 8
        for (int e=0; e<128; e++){
            float2 yv2 = *(const float2*)&ynT[e*KP + i*2];
            float4 wv4 = *(const float4*)&wT1[e*KP + j*4];
            a00=fmaf(yv2.x,wv4.x,a00); a01=fmaf(yv2.x,wv4.y,a01); a02=fmaf(yv2.x,wv4.z,a02); a03=fmaf(yv2.x,wv4.w,a03);
            a10=fmaf(yv2.y,wv4.x,a10); a11=fmaf(yv2.y,wv4.y,a11); a12=fmaf(yv2.y,wv4.z,a12); a13=fmaf(yv2.y,wv4.w,a13);
        }
        #define SS(v) ((v)*rsqrtf(1.f+(v)*(v)))
        tT[(j*4+0)*KP + i*2+0]=SS(a00); tT[(j*4+1)*KP + i*2+0]=SS(a01); tT[(j*4+2)*KP + i*2+0]=SS(a02); tT[(j*4+3)*KP + i*2+0]=SS(a03);
        tT[(j*4+0)*KP + i*2+1]=SS(a10); tT[(j*4+1)*KP + i*2+1]=SS(a11); tT[(j*4+2)*KP + i*2+1]=SS(a12); tT[(j*4+3)*KP + i*2+1]=SS(a13);
        #undef SS
    }
    __syncthreads();

    {
        int i = tid>>4, j = tid&15;
        float4 mbv = *(const float4*)&mbs[j*4];
        float a00=mbv.x,a01=mbv.y,a02=mbv.z,a03=mbv.w;
        float a10=mbv.x,a11=mbv.y,a12=mbv.z,a13=mbv.w;
        #pragma unroll 8
        for (int e=0; e<64; e++){
            float2 tv2 = *(const float2*)&tT[e*KP + i*2];
            float4 wv4 = *(const float4*)&wT2[e*KP + j*4];
            a00=fmaf(tv2.x,wv4.x,a00); a01=fmaf(tv2.x,wv4.y,a01); a02=fmaf(tv2.x,wv4.z,a02); a03=fmaf(tv2.x,wv4.w,a03);
            a10=fmaf(tv2.y,wv4.x,a10); a11=fmaf(tv2.y,wv4.y,a11); a12=fmaf(tv2.y,wv4.z,a12); a13=fmaf(tv2.y,wv4.w,a13);
        }
        int gt0 = tok0 + i*2;
        float4 h0 = *(const float4*)&g_h[(size_t)(gt0+0)*HH + j*4];
        float4 h1 = *(const float4*)&g_h[(size_t)(gt0+1)*HH + j*4];
        h0.x+=a00; h0.y+=a01; h0.z+=a02; h0.w+=a03;
        h1.x+=a10; h1.y+=a11; h1.z+=a12; h1.w+=a13;
        *(float4*)&g_h[(size_t)(gt0+0)*HH + j*4] = h0;
        *(float4*)&g_h[(size_t)(gt0+1)*HH + j*4] = h1;
    }
}

// ---------------- final ----------------
__global__ void k_final(const float* __restrict__ wo, float* __restrict__ out){
    int tid = threadIdx.x;
    int tok = blockIdx.x*8 + (tid>>5); int lane = tid&31;
    float v = g_h[tok*HH + lane]*wo[lane] + g_h[tok*HH + lane + 32]*wo[lane+32];
    #pragma unroll
    for (int o=16; o; o>>=1) v += __shfl_xor_sync(~0u, v, o);
    if (lane == 0) out[tok] = v;
}

extern "C" void kernel_launch(void* const* d_in, const int* in_sizes, int n_in,
                              void* d_out, int out_size){
    const float* x    = (const float*)d_in[0];
    const float* w_in = (const float*)d_in[1];
    const float* w_out= (const float*)d_in[2];
    const float* ipw  = (const float*)d_in[3];
    const float* cw   = (const float*)d_in[4];
    const float* cb   = (const float*)d_in[5];
    const float* dtb  = (const float*)d_in[6];
    const float* alog = (const float*)d_in[7];
    const float* dsk  = (const float*)d_in[8];
    const float* ist  = (const float*)d_in[9];
    const float* nw   = (const float*)d_in[10];
    const float* opw  = (const float*)d_in[11];
    const float* mw   = (const float*)d_in[12];
    const float* mb   = (const float*)d_in[13];
    float* out = (float*)d_out;

    cudaFuncSetAttribute(k_out, cudaFuncAttributeMaxDynamicSharedMemorySize,
                         SMEM_OUT_FLOATS*4);
    cudaFuncSetAttribute(k_inproj, cudaFuncAttributeMaxDynamicSharedMemorySize,
                         INPROJ_SMEM);

    k_nop<<<1,1>>>();
    k_nop<<<1,1>>>();
    k_embed<<<NTOK*HH/256, 256>>>(x, w_in);
    for (int i=0; i<DBLK; i++){
        k_inproj<<<NTOK/32, 320, INPROJ_SMEM>>>(ipw + (size_t)i*DPROJ*HH);
        k_conv<<<(NTOK/16)*CONV_DIM/256, 256>>>(cw + i*CONV_DIM*DCONV, cb + i*CONV_DIM);
        k_intra<<<BB*64*4, 256>>>(dtb + i*NHEADS, alog + i*NHEADS, dsk + i*NHEADS);
        k_scan<<<BB*NHEADS, 256>>>(ist + (size_t)i*NHEADS*HEADDIM*NSTATE);
        k_out<<<NTOK/64, 512, SMEM_OUT_FLOATS*4>>>(nw + i*DINNER,
                                                   opw + (size_t)i*HH*DINNER,
                                                   mw + i*HH*HH, mb + i*HH);
    }
    k_final<<<NTOK/8, 256>>>(w_out, out);
}

// round 15
// speedup vs baseline: 1.0796x; 1.0474x over previous
#include <cuda_runtime.h>
#include <math.h>

#define BB 4
#define LL 8192
#define HH 64
#define NSTATE 16
#define DBLK 4
#define DCONV 16
#define DINNER 128
#define HEADDIM 16
#define NHEADS 8
#define CONV_DIM 160
#define DPROJ 296
#define QSUB 32
#define NSUB (LL/QSUB)
#define NTOK (BB*LL)

// ---------------- scratch (device globals; no allocation) ----------------
__device__ float g_h[NTOK*HH];
__device__ float g_zx[NTOK*DPROJ];
__device__ float g_xBC[NTOK*CONV_DIM];
__device__ float g_acs[BB*NSUB*NHEADS*QSUB];
__device__ float g_stl[BB*NSUB*NHEADS*256];
__device__ float g_prev[BB*NSUB*NHEADS*256];
__device__ float g_y[NTOK*DINNER];

// ---------------- nop (window shift: capture k_inproj) ----------------
__global__ void k_nop(){}

// ---------------- embed ----------------
__global__ void k_embed(const float* __restrict__ x, const float* __restrict__ w_in){
    int i = blockIdx.x*blockDim.x + threadIdx.x;
    int tok = i >> 6; int d = i & 63;
    g_h[i] = x[tok] * w_in[d];
}

// ---------------- in_proj: 32 tok/block, 2D register tile 4e x 8t, FFMA2 ----------------
#define HTP 36
#define WTP 300
#define INPROJ_SMEM ((64*HTP + 64*WTP + 32)*4)
__global__ void __launch_bounds__(320) k_inproj(const float* __restrict__ w){
    extern __shared__ float smp[];
    float* hs_t = smp;               // [64 d][HTP] transposed h tile
    float* ws_t = smp + 64*HTP;      // [64 d][WTP] transposed weights
    int tid = threadIdx.x;
    int t0 = blockIdx.x*32;
    for (int i=tid; i<2048; i+=320){ int t=i>>6, d=i&63; hs_t[d*HTP+t] = g_h[(size_t)t0*64 + i]; }
    for (int i=tid; i<DPROJ*64; i+=320){ int e=i>>6, d=i&63; ws_t[d*WTP+e] = w[i]; }
    __syncthreads();
    int j = tid % 80;           // e-quad
    int i4 = tid / 80;          // token-oct
    int e0 = j*4;
    if (e0 < DPROJ){
        unsigned long long acc[4][4];
        #pragma unroll
        for (int e=0; e<4; e++)
            #pragma unroll
            for (int t=0; t<4; t++) acc[e][t] = 0ULL;
        #pragma unroll 4
        for (int d=0; d<64; d++){
            float4 wv = *(const float4*)&ws_t[d*WTP + e0];
            unsigned long long w2[4];
            asm("mov.b64 %0, {%1, %1};" : "=l"(w2[0]) : "r"(__float_as_uint(wv.x)));
            asm("mov.b64 %0, {%1, %1};" : "=l"(w2[1]) : "r"(__float_as_uint(wv.y)));
            asm("mov.b64 %0, {%1, %1};" : "=l"(w2[2]) : "r"(__float_as_uint(wv.z)));
            asm("mov.b64 %0, {%1, %1};" : "=l"(w2[3]) : "r"(__float_as_uint(wv.w)));
            const ulonglong2* hp = (const ulonglong2*)&hs_t[d*HTP + i4*8];
            ulonglong2 h01 = hp[0];
            ulonglong2 h23 = hp[1];
            #pragma unroll
            for (int e=0; e<4; e++){
                asm("fma.rn.f32x2 %0, %1, %2, %0;" : "+l"(acc[e][0]) : "l"(h01.x), "l"(w2[e]));
                asm("fma.rn.f32x2 %0, %1, %2, %0;" : "+l"(acc[e][1]) : "l"(h01.y), "l"(w2[e]));
                asm("fma.rn.f32x2 %0, %1, %2, %0;" : "+l"(acc[e][2]) : "l"(h23.x), "l"(w2[e]));
                asm("fma.rn.f32x2 %0, %1, %2, %0;" : "+l"(acc[e][3]) : "l"(h23.y), "l"(w2[e]));
            }
        }
        #pragma unroll
        for (int e=0; e<4; e++){
            #pragma unroll
            for (int t=0; t<4; t++){
                float2 v = *(float2*)&acc[e][t];
                g_zx[(size_t)(t0 + i4*8 + 2*t    )*DPROJ + e0 + e] = v.x;
                g_zx[(size_t)(t0 + i4*8 + 2*t + 1)*DPROJ + e0 + e] = v.y;
            }
        }
    }
}

// ---------------- depthwise causal conv + bias + silu (16 tokens/thread) ----------------
__global__ void __launch_bounds__(256) k_conv(const float* __restrict__ cw, const float* __restrict__ cb){
    __shared__ float cws[CONV_DIM*17];
    __shared__ float cbs[CONV_DIM];
    int tid = threadIdx.x;
    for (int i=tid; i<CONV_DIM*DCONV; i+=256){ int ch=i>>4, k=i&15; cws[ch*17+k] = cw[i]; }
    if (tid < CONV_DIM) cbs[tid] = cb[tid];
    __syncthreads();
    int idx = blockIdx.x*blockDim.x + tid;
    int ch  = idx % CONV_DIM;
    int grp = idx / CONV_DIM;
    int tok0 = grp*16;
    int b = tok0 / LL, l0 = tok0 % LL;
    float wv[DCONV];
    #pragma unroll
    for (int k=0; k<DCONV; k++) wv[k] = cws[ch*17 + k];
    float in[DCONV+15];
    #pragma unroll
    for (int k=0; k<DCONV+15; k++){
        int ls = l0 - (DCONV-1) + k;
        in[k] = (ls >= 0) ? g_zx[(size_t)(b*LL + ls)*DPROJ + DINNER + ch] : 0.f;
    }
    float bias = cbs[ch];
    #pragma unroll
    for (int j=0; j<16; j++){
        float acc = bias;
        #pragma unroll
        for (int k=0; k<DCONV; k++) acc = fmaf(wv[k], in[j+k], acc);
        g_xBC[(size_t)(tok0+j)*CONV_DIM + ch] = acc / (1.f + __expf(-acc));
    }
}

// ---------------- intra-subchunk (Q=32): R8 version (best measured: 54.7us) ----------------
__global__ void __launch_bounds__(256) k_intra(const float* __restrict__ dtb,
                                               const float* __restrict__ alog,
                                               const float* __restrict__ dskip){
    int blk = blockIdx.x;
    int hp = blk & 3;
    int grp = blk >> 2;
    int b = grp >> 6, g = grp & 63;
    int tokbase = b*LL + g*128;
    int tid = threadIdx.x;
    int hl = tid >> 7;
    int l  = tid & 127;
    int lane = tid & 31;
    int h = hp*2 + hl;
    __shared__ float Bs[128*16];
    __shared__ float Cs[128*16];
    __shared__ float Xs[2][128*16];
    __shared__ float2 ps[2][128];
    __shared__ float dd[2][128];

    float vraw = g_zx[(size_t)(tokbase+l)*DPROJ + DINNER + CONV_DIM + h] + dtb[h];
    float dt = (vraw > 20.f) ? vraw : log1pf(__expf(vraw));
    float sc = dt * (-__expf(alog[h]));
    #pragma unroll
    for (int off=1; off<32; off<<=1){
        float u = __shfl_up_sync(0xffffffffu, sc, off);
        if (lane >= off) sc += u;
    }
    float tot = __shfl_sync(0xffffffffu, sc, 31);
    ps[hl][l] = make_float2(sc, dt);
    dd[hl][l] = __expf(tot - sc) * dt;
    int gsub = b*NSUB + g*4 + (l>>5);
    g_acs[(gsub*NHEADS + h)*QSUB + lane] = sc;

    {
        const float* row = &g_xBC[(size_t)(tokbase+l)*CONV_DIM];
        if (hl == 0){
            #pragma unroll
            for (int k=0;k<4;k++) *(float4*)&Bs[l*16+4*k] = *(const float4*)&row[DINNER+4*k];
        } else {
            #pragma unroll
            for (int k=0;k<4;k++) *(float4*)&Cs[l*16+4*k] = *(const float4*)&row[DINNER+NSTATE+4*k];
        }
        #pragma unroll
        for (int k=0;k<4;k++) *(float4*)&Xs[hl][l*16+4*k] = *(const float4*)&row[h*HEADDIM+4*k];
    }
    __syncthreads();

    {
        int hh = tid>>7, q=(tid>>5)&3, n=(tid>>1)&15, ph=tid&1;
        const float* Xq = Xs[hh];
        float a0=0,a1=0,a2=0,a3=0,a4=0,a5=0,a6=0,a7=0;
        int l0 = q*32;
        #pragma unroll 4
        for (int ll=0; ll<32; ll++){
            int lr = l0+ll;
            float bd = Bs[lr*16+n]*dd[hh][lr];
            float4 xa = *(const float4*)&Xq[lr*16+ph*8];
            float4 xb = *(const float4*)&Xq[lr*16+ph*8+4];
            a0=fmaf(bd,xa.x,a0); a1=fmaf(bd,xa.y,a1); a2=fmaf(bd,xa.z,a2); a3=fmaf(bd,xa.w,a3);
            a4=fmaf(bd,xb.x,a4); a5=fmaf(bd,xb.y,a5); a6=fmaf(bd,xb.z,a6); a7=fmaf(bd,xb.w,a7);
        }
        int base = ((b*NSUB + g*4 + q)*NHEADS + hp*2+hh)*256 + n*16 + ph*8;
        *(float4*)&g_stl[base]   = make_float4(a0,a1,a2,a3);
        *(float4*)&g_stl[base+4] = make_float4(a4,a5,a6,a7);
    }

    {
        const float* Xsh = Xs[hl];
        float4 c0 = *(const float4*)&Cs[l*16+0];
        float4 c1 = *(const float4*)&Cs[l*16+4];
        float4 c2 = *(const float4*)&Cs[l*16+8];
        float4 c3 = *(const float4*)&Cs[l*16+12];
        float al = sc;
        float dsk = dskip[h];
        float4 y0 = *(const float4*)&Xsh[l*16+0];
        float4 y1 = *(const float4*)&Xsh[l*16+4];
        float4 y2 = *(const float4*)&Xsh[l*16+8];
        float4 y3 = *(const float4*)&Xsh[l*16+12];
        y0.x*=dsk; y0.y*=dsk; y0.z*=dsk; y0.w*=dsk;
        y1.x*=dsk; y1.y*=dsk; y1.z*=dsk; y1.w*=dsk;
        y2.x*=dsk; y2.y*=dsk; y2.z*=dsk; y2.w*=dsk;
        y3.x*=dsk; y3.y*=dsk; y3.z*=dsk; y3.w*=dsk;
        int s0 = l & ~31;
        for (int s=s0; s<=l; s++){
            float2 pd = ps[hl][s];
            float4 b0 = *(const float4*)&Bs[s*16+0];
            float4 b1 = *(const float4*)&Bs[s*16+4];
            float4 b2 = *(const float4*)&Bs[s*16+8];
            float4 b3 = *(const float4*)&Bs[s*16+12];
            float p0 = fmaf(c0.x,b0.x, c0.y*b0.y); p0 = fmaf(c0.z,b0.z,p0); p0 = fmaf(c0.w,b0.w,p0);
            float p1 = fmaf(c1.x,b1.x, c1.y*b1.y); p1 = fmaf(c1.z,b1.z,p1); p1 = fmaf(c1.w,b1.w,p1);
            float p2 = fmaf(c2.x,b2.x, c2.y*b2.y); p2 = fmaf(c2.z,b2.z,p2); p2 = fmaf(c2.w,b2.w,p2);
            float p3 = fmaf(c3.x,b3.x, c3.y*b3.y); p3 = fmaf(c3.z,b3.z,p3); p3 = fmaf(c3.w,b3.w,p3);
            float dot = (p0+p1) + (p2+p3);
            float wgt = dot * (__expf(al - pd.x) * pd.y);
            float4 x0 = *(const float4*)&Xsh[s*16+0];
            float4 x1 = *(const float4*)&Xsh[s*16+4];
            float4 x2 = *(const float4*)&Xsh[s*16+8];
            float4 x3 = *(const float4*)&Xsh[s*16+12];
            y0.x = fmaf(wgt,x0.x,y0.x); y0.y = fmaf(wgt,x0.y,y0.y); y0.z = fmaf(wgt,x0.z,y0.z); y0.w = fmaf(wgt,x0.w,y0.w);
            y1.x = fmaf(wgt,x1.x,y1.x); y1.y = fmaf(wgt,x1.y,y1.y); y1.z = fmaf(wgt,x1.z,y1.z); y1.w = fmaf(wgt,x1.w,y1.w);
            y2.x = fmaf(wgt,x2.x,y2.x); y2.y = fmaf(wgt,x2.y,y2.y); y2.z = fmaf(wgt,x2.z,y2.z); y2.w = fmaf(wgt,x2.w,y2.w);
            y3.x = fmaf(wgt,x3.x,y3.x); y3.y = fmaf(wgt,x3.y,y3.y); y3.z = fmaf(wgt,x3.z,y3.z); y3.w = fmaf(wgt,x3.w,y3.w);
        }
        float* yo = &g_y[(size_t)(tokbase+l)*DINNER + h*HEADDIM];
        *(float4*)&yo[0]  = y0;
        *(float4*)&yo[4]  = y1;
        *(float4*)&yo[8]  = y2;
        *(float4*)&yo[12] = y3;
    }
}

// ---------------- inter-subchunk scan ----------------
__global__ void k_scan(const float* __restrict__ ist){
    int b = blockIdx.x>>3, h = blockIdx.x&7;
    int tid = threadIdx.x;
    __shared__ float ats[NSUB];
    ats[tid] = __expf(g_acs[((b*NSUB + tid)*NHEADS + h)*QSUB + QSUB-1]);
    __syncthreads();
    float S = ist[h*256 + (tid&15)*16 + (tid>>4)];
    size_t idx0 = ((size_t)(b*NSUB)*NHEADS + h)*256 + tid;
    const size_t stride = (size_t)NHEADS*256;
    for (int c0=0; c0<NSUB; c0+=16){
        float buf[16];
        #pragma unroll
        for (int j=0; j<16; j++) buf[j] = g_stl[idx0 + (size_t)(c0+j)*stride];
        #pragma unroll
        for (int j=0; j<16; j++){
            g_prev[idx0 + (size_t)(c0+j)*stride] = S;
            S = fmaf(S, ats[c0+j], buf[j]);
        }
    }
}

// ---------------- Y_off + gate + RMSnorm + out_proj + softsign + MLP + residual ----------------
#define KP 68
#define SMEM_OUT_FLOATS 27648
__global__ void __launch_bounds__(512,2) k_out(const float* __restrict__ nw,
                                               const float* __restrict__ ow,
                                               const float* __restrict__ mw,
                                               const float* __restrict__ mb){
    extern __shared__ float sm[];
    float* ysH  = sm;              // phase1 pass: [32][132]
    float* zsH  = sm + 4224;       // phase1 pass: [32][132]
    float* wT1  = sm;              // phase2 overlay: [128][KP]
    float* ynT  = sm + 8704;       // [128][KP]
    float* prevs= sm + 17408;      // [16][260] plain [n][p]
    float* cmr  = sm + 21568;      // [64][16]
    float* ear  = sm + 22592;      // [64][8]
    float* nws  = sm + 23104;      // 128
    float* mbs  = sm + 23232;      // 64
    float* wT2  = sm + 17408;      // phase2 overlay of prevs: [64][KP]
    float* tT   = sm + 23296;      // [64][KP]
    int tid = threadIdx.x;
    int tok0 = blockIdx.x*64;
    int b = tok0 >> 13;
    int lbase = tok0 & (LL-1);
    int sub0 = b*NSUB + (lbase>>5);

    for (int i=tid; i<4096; i+=512){
        int sl=i>>11, r=i&2047, hh=r>>8, el=r&255;
        prevs[(sl*8+hh)*260 + el] = g_prev[((size_t)(sub0+sl)*NHEADS+hh)*256 + el];
    }
    for (int i=tid; i<1024; i+=512){ int t=i>>4, n=i&15;
        cmr[i] = g_xBC[(size_t)(tok0+t)*CONV_DIM + DINNER + NSTATE + n]; }
    if (tid < 512){ int t=tid>>3, hh=tid&7;
        ear[tid] = __expf(g_acs[((size_t)(sub0 + (t>>5))*NHEADS + hh)*QSUB + (t&31)]); }
    if (tid < 128) nws[tid] = nw[tid];
    if (tid < 64)  mbs[tid] = mb[tid];

    for (int pass=0; pass<2; pass++){
        __syncthreads();
        for (int i=tid; i<1024; i+=512){
            int t = i>>5, c4 = i&31;
            *(float4*)&ysH[t*132 + c4*4] = *(const float4*)&g_y[(size_t)(tok0+pass*32+t)*DINNER + c4*4];
            *(float4*)&zsH[t*132 + c4*4] = *(const float4*)&g_zx[(size_t)(tok0+pass*32+t)*DPROJ + c4*4];
        }
        __syncthreads();
        {
            int tokL = tid>>4, sub = tid&15;
            int tok = pass*32 + tokL;
            int h = sub>>1, p0 = (sub&1)*8;
            float cm[16];
            #pragma unroll
            for (int n=0; n<16; n++) cm[n] = cmr[tok*16+n];
            const float* pv = &prevs[(pass*8+h)*260];
            float4 acc0 = make_float4(0.f,0.f,0.f,0.f);
            float4 acc1 = make_float4(0.f,0.f,0.f,0.f);
            #pragma unroll
            for (int n=0; n<16; n++){
                float4 a = *(const float4*)&pv[n*16+p0];
                float4 c = *(const float4*)&pv[n*16+p0+4];
                acc0.x = fmaf(cm[n], a.x, acc0.x); acc0.y = fmaf(cm[n], a.y, acc0.y);
                acc0.z = fmaf(cm[n], a.z, acc0.z); acc0.w = fmaf(cm[n], a.w, acc0.w);
                acc1.x = fmaf(cm[n], c.x, acc1.x); acc1.y = fmaf(cm[n], c.y, acc1.y);
                acc1.z = fmaf(cm[n], c.z, acc1.z); acc1.w = fmaf(cm[n], c.w, acc1.w);
            }
            float e_a = ear[tok*8+h];
            float av[8] = {acc0.x,acc0.y,acc0.z,acc0.w, acc1.x,acc1.y,acc1.z,acc1.w};
            float yv[8]; float ss = 0.f;
            #pragma unroll
            for (int j=0; j<8; j++){
                int ch = sub*8 + j;
                float y = ysH[tokL*132+ch] + e_a*av[j];
                float z = zsH[tokL*132+ch];
                y *= z / (1.f + __expf(-z));
                yv[j] = y; ss = fmaf(y, y, ss);
            }
            ss += __shfl_xor_sync(0xffffffffu, ss, 1, 16);
            ss += __shfl_xor_sync(0xffffffffu, ss, 2, 16);
            ss += __shfl_xor_sync(0xffffffffu, ss, 4, 16);
            ss += __shfl_xor_sync(0xffffffffu, ss, 8, 16);
            float scale = rsqrtf(ss*(1.f/128.f) + 1e-5f);
            #pragma unroll
            for (int j=0; j<8; j++){
                int ch = sub*8 + j;
                ynT[ch*KP + tok] = yv[j]*scale*nws[ch];
            }
        }
    }
    __syncthreads();

    for (int i=tid; i<128*64; i+=512){ int d=i>>7, e=i&127; wT1[e*KP+d] = ow[i]; }
    for (int i=tid; i<64*64;  i+=512){ int d=i>>6, e=i&63;  wT2[e*KP+d] = mw[i]; }
    __syncthreads();

    {
        int i = tid>>4, j = tid&15;
        float a00=0,a01=0,a02=0,a03=0, a10=0,a11=0,a12=0,a13=0;
        #pragma unroll 8
        for (int e=0; e<128; e++){
            float2 yv2 = *(const float2*)&ynT[e*KP + i*2];
            float4 wv4 = *(const float4*)&wT1[e*KP + j*4];
            a00=fmaf(yv2.x,wv4.x,a00); a01=fmaf(yv2.x,wv4.y,a01); a02=fmaf(yv2.x,wv4.z,a02); a03=fmaf(yv2.x,wv4.w,a03);
            a10=fmaf(yv2.y,wv4.x,a10); a11=fmaf(yv2.y,wv4.y,a11); a12=fmaf(yv2.y,wv4.z,a12); a13=fmaf(yv2.y,wv4.w,a13);
        }
        #define SS(v) ((v)*rsqrtf(1.f+(v)*(v)))
        tT[(j*4+0)*KP + i*2+0]=SS(a00); tT[(j*4+1)*KP + i*2+0]=SS(a01); tT[(j*4+2)*KP + i*2+0]=SS(a02); tT[(j*4+3)*KP + i*2+0]=SS(a03);
        tT[(j*4+0)*KP + i*2+1]=SS(a10); tT[(j*4+1)*KP + i*2+1]=SS(a11); tT[(j*4+2)*KP + i*2+1]=SS(a12); tT[(j*4+3)*KP + i*2+1]=SS(a13);
        #undef SS
    }
    __syncthreads();

    {
        int i = tid>>4, j = tid&15;
        float4 mbv = *(const float4*)&mbs[j*4];
        float a00=mbv.x,a01=mbv.y,a02=mbv.z,a03=mbv.w;
        float a10=mbv.x,a11=mbv.y,a12=mbv.z,a13=mbv.w;
        #pragma unroll 8
        for (int e=0; e<64; e++){
            float2 tv2 = *(const float2*)&tT[e*KP + i*2];
            float4 wv4 = *(const float4*)&wT2[e*KP + j*4];
            a00=fmaf(tv2.x,wv4.x,a00); a01=fmaf(tv2.x,wv4.y,a01); a02=fmaf(tv2.x,wv4.z,a02); a03=fmaf(tv2.x,wv4.w,a03);
            a10=fmaf(tv2.y,wv4.x,a10); a11=fmaf(tv2.y,wv4.y,a11); a12=fmaf(tv2.y,wv4.z,a12); a13=fmaf(tv2.y,wv4.w,a13);
        }
        int gt0 = tok0 + i*2;
        float4 h0 = *(const float4*)&g_h[(size_t)(gt0+0)*HH + j*4];
        float4 h1 = *(const float4*)&g_h[(size_t)(gt0+1)*HH + j*4];
        h0.x+=a00; h0.y+=a01; h0.z+=a02; h0.w+=a03;
        h1.x+=a10; h1.y+=a11; h1.z+=a12; h1.w+=a13;
        *(float4*)&g_h[(size_t)(gt0+0)*HH + j*4] = h0;
        *(float4*)&g_h[(size_t)(gt0+1)*HH + j*4] = h1;
    }
}

// ---------------- final ----------------
__global__ void k_final(const float* __restrict__ wo, float* __restrict__ out){
    int tid = threadIdx.x;
    int tok = blockIdx.x*8 + (tid>>5); int lane = tid&31;
    float v = g_h[tok*HH + lane]*wo[lane] + g_h[tok*HH + lane + 32]*wo[lane+32];
    #pragma unroll
    for (int o=16; o; o>>=1) v += __shfl_xor_sync(~0u, v, o);
    if (lane == 0) out[tok] = v;
}

extern "C" void kernel_launch(void* const* d_in, const int* in_sizes, int n_in,
                              void* d_out, int out_size){
    const float* x    = (const float*)d_in[0];
    const float* w_in = (const float*)d_in[1];
    const float* w_out= (const float*)d_in[2];
    const float* ipw  = (const float*)d_in[3];
    const float* cw   = (const float*)d_in[4];
    const float* cb   = (const float*)d_in[5];
    const float* dtb  = (const float*)d_in[6];
    const float* alog = (const float*)d_in[7];
    const float* dsk  = (const float*)d_in[8];
    const float* ist  = (const float*)d_in[9];
    const float* nw   = (const float*)d_in[10];
    const float* opw  = (const float*)d_in[11];
    const float* mw   = (const float*)d_in[12];
    const float* mb   = (const float*)d_in[13];
    float* out = (float*)d_out;

    cudaFuncSetAttribute(k_out, cudaFuncAttributeMaxDynamicSharedMemorySize,
                         SMEM_OUT_FLOATS*4);
    cudaFuncSetAttribute(k_inproj, cudaFuncAttributeMaxDynamicSharedMemorySize,
                         INPROJ_SMEM);

    k_nop<<<1,1>>>();
    k_nop<<<1,1>>>();
    k_embed<<<NTOK*HH/256, 256>>>(x, w_in);
    for (int i=0; i<DBLK; i++){
        k_inproj<<<NTOK/32, 320, INPROJ_SMEM>>>(ipw + (size_t)i*DPROJ*HH);
        k_conv<<<(NTOK/16)*CONV_DIM/256, 256>>>(cw + i*CONV_DIM*DCONV, cb + i*CONV_DIM);
        k_intra<<<BB*64*4, 256>>>(dtb + i*NHEADS, alog + i*NHEADS, dsk + i*NHEADS);
        k_scan<<<BB*NHEADS, 256>>>(ist + (size_t)i*NHEADS*HEADDIM*NSTATE);
        k_out<<<NTOK/64, 512, SMEM_OUT_FLOATS*4>>>(nw + i*DINNER,
                                                   opw + (size_t)i*HH*DINNER,
                                                   mw + i*HH*HH, mb + i*HH);
    }
    k_final<<<NTOK/8, 256>>>(w_out, out);
}